// round 1
// baseline (speedup 1.0000x reference)
#include <cuda_runtime.h>

// IFS trajectory kernel.
// inputs: d_in[0] = coef (BATCH, 12) f32, d_in[1] = h (ITERS, BATCH) f32
// output: (BATCH, ITERS+1, 2) f32
//
// One thread per batch element. h reads are coalesced (stride-1 in b).
// Output stores are float2 per step at 8*(ITERS+1) byte stride per thread;
// consecutive iterations of the same thread fill 32B sectors, and the live
// write footprint fits in L2, so lines should assemble before DRAM writeback.

__global__ void ifs_traj_kernel(const float* __restrict__ coef,
                                const float* __restrict__ h,
                                float2* __restrict__ out,
                                int batch, int iters) {
    int b = blockIdx.x * blockDim.x + threadIdx.x;
    if (b >= batch) return;

    // 12 coefs per element, 16B-aligned (12 floats * 4B, b*48 is 16B aligned)
    const float4* c4 = reinterpret_cast<const float4*>(coef + (size_t)b * 12);
    float4 ca = c4[0];   // c0..c3
    float4 cb = c4[1];   // c4..c7
    float4 cc = c4[2];   // c8..c11

    // A = (c0,c1,c2,c3,c4,c5), B = (c6,c7,c8,c9,c10,c11)
    float A0 = ca.x, A1 = ca.y, A2 = ca.z, A3 = ca.w, A4 = cb.x, A5 = cb.y;
    float B0 = cb.z, B1 = cb.w, B2 = cc.x, B3 = cc.y, B4 = cc.z, B5 = cc.w;

    float j0 = fabsf(A0 * A3 - A1 * A2);
    float j1 = fabsf(B0 * B3 - B1 * B2);
    float p  = j0 / (j0 + j1);

    float x = 0.05f, y = 0.05f;

    float2* o = out + (size_t)b * (iters + 1);
    o[0] = make_float2(0.05f, 0.05f);

    const float* hp = h + b;
    #pragma unroll 4
    for (int t = 0; t < iters; ++t) {
        float ht = __ldg(hp + (size_t)t * batch);
        bool m = ht > p;
        float d0 = m ? B0 : A0;
        float d1 = m ? B1 : A1;
        float d2 = m ? B2 : A2;
        float d3 = m ? B3 : A3;
        float d4 = m ? B4 : A4;
        float d5 = m ? B5 : A5;
        float xn = fmaf(d0, x, fmaf(d1, y, d4));
        float yn = fmaf(d2, x, fmaf(d3, y, d5));
        x = xn; y = yn;
        o[t + 1] = make_float2(x, y);
    }
}

extern "C" void kernel_launch(void* const* d_in, const int* in_sizes, int n_in,
                              void* d_out, int out_size) {
    const float* coef = (const float*)d_in[0];
    const float* h    = (const float*)d_in[1];
    float2* out       = (float2*)d_out;

    int batch = in_sizes[0] / 12;
    int iters = in_sizes[1] / batch;

    int threads = 256;
    int blocks = (batch + threads - 1) / threads;
    ifs_traj_kernel<<<blocks, threads>>>(coef, h, out, batch, iters);
}

// round 2
// speedup vs baseline: 1.9126x; 1.9126x over previous
#include <cuda_runtime.h>

// IFS trajectory kernel, smem-tiled in time.
// inputs: d_in[0] = coef (BATCH, 12) f32, d_in[1] = h (ITERS, BATCH) f32
// output: (BATCH, ITERS+1, 2) f32
//
// Per block (256 batch elems), per tile of T=20 time steps:
//   1. bulk coalesced load of h tile into smem (MLP=T per thread)
//   2. T recurrence steps reading h from smem, results staged in smem
//   3. coalesced float2 flush of the staged (x,y) tile to global

#define BLOCK 256
#define TILE  20

__global__ __launch_bounds__(BLOCK) void ifs_traj_kernel(
    const float* __restrict__ coef,
    const float* __restrict__ h,
    float2* __restrict__ out,
    int batch, int iters)
{
    __shared__ float  sh[TILE][BLOCK];        // h tile: [t][b_local]
    __shared__ float2 so[BLOCK][TILE + 1];    // out tile, +1 pad vs bank conflicts

    const int tid = threadIdx.x;
    const int b   = blockIdx.x * BLOCK + tid;
    const bool active = (b < batch);

    // --- per-element setup ---
    float A0=0,A1=0,A2=0,A3=0,A4=0,A5=0,B0=0,B1=0,B2=0,B3=0,B4=0,B5=0,p=0;
    if (active) {
        const float4* c4 = reinterpret_cast<const float4*>(coef + (size_t)b * 12);
        float4 ca = c4[0], cb = c4[1], cc = c4[2];
        A0=ca.x; A1=ca.y; A2=ca.z; A3=ca.w; A4=cb.x; A5=cb.y;
        B0=cb.z; B1=cb.w; B2=cc.x; B3=cc.y; B4=cc.z; B5=cc.w;
        float j0 = fabsf(A0*A3 - A1*A2);
        float j1 = fabsf(B0*B3 - B1*B2);
        p = j0 / (j0 + j1);
        // initial point
        out[(size_t)b * (iters + 1)] = make_float2(0.05f, 0.05f);
    }

    float x = 0.05f, y = 0.05f;

    for (int t0 = 0; t0 < iters; t0 += TILE) {
        const int tc = min(TILE, iters - t0);

        // --- phase 1: bulk load h tile (coalesced across tid, MLP=tc) ---
        if (active) {
            #pragma unroll
            for (int tt = 0; tt < TILE; ++tt) {
                if (tt < tc)
                    sh[tt][tid] = __ldg(h + (size_t)(t0 + tt) * batch + b);
            }
        }
        __syncthreads();

        // --- phase 2: recurrence out of smem ---
        if (active) {
            #pragma unroll
            for (int tt = 0; tt < TILE; ++tt) {
                if (tt < tc) {
                    float ht = sh[tt][tid];
                    bool m = ht > p;
                    float d0 = m ? B0 : A0;
                    float d1 = m ? B1 : A1;
                    float d2 = m ? B2 : A2;
                    float d3 = m ? B3 : A3;
                    float d4 = m ? B4 : A4;
                    float d5 = m ? B5 : A5;
                    float xn = fmaf(d0, x, fmaf(d1, y, d4));
                    float yn = fmaf(d2, x, fmaf(d3, y, d5));
                    x = xn; y = yn;
                    so[tid][tt] = make_float2(x, y);
                }
            }
        }
        __syncthreads();

        // --- phase 3: coalesced flush of staged outputs ---
        // float2 index space: idx -> (b_local = idx / tc, tt = idx % tc)
        const int total = BLOCK * tc;
        for (int idx = tid; idx < total; idx += BLOCK) {
            int b_local = idx / tc;
            int tt      = idx - b_local * tc;
            int bg      = blockIdx.x * BLOCK + b_local;
            if (bg < batch) {
                out[(size_t)bg * (iters + 1) + 1 + t0 + tt] = so[b_local][tt];
            }
        }
        __syncthreads();
    }
}

extern "C" void kernel_launch(void* const* d_in, const int* in_sizes, int n_in,
                              void* d_out, int out_size) {
    const float* coef = (const float*)d_in[0];
    const float* h    = (const float*)d_in[1];
    float2* out       = (float2*)d_out;

    int batch = in_sizes[0] / 12;
    int iters = in_sizes[1] / batch;

    int blocks = (batch + BLOCK - 1) / BLOCK;
    ifs_traj_kernel<<<blocks, BLOCK>>>(coef, h, out, batch, iters);
}

// round 3
// speedup vs baseline: 3.0847x; 1.6128x over previous
#include <cuda_runtime.h>

// IFS trajectory kernel, per-warp time-tiled.
// inputs: d_in[0] = coef (BATCH, 12) f32, d_in[1] = h (ITERS, BATCH) f32
// output: (BATCH, ITERS+1, 2) f32
//
// Per warp (32 batch elems), per tile of TILE=16 steps:
//   1. h tile -> 16 registers (coalesced LDG burst, MLP=16)
//   2. 16 recurrence steps (dual-FMA + 2 selects), (x,y) staged in per-warp smem
//   3. coalesced flush: each half-warp writes one b's 16 float2 = 128B contiguous
// No block barriers, only __syncwarp. Flush indexing uses shifts (TILE pow2).

#define BLOCK 256
#define TILE  16
#define WARPS (BLOCK / 32)

__global__ __launch_bounds__(BLOCK, 3) void ifs_traj_kernel(
    const float* __restrict__ coef,
    const float* __restrict__ h,
    float2* __restrict__ out,
    int batch, int iters)
{
    // per-warp staging: [lane][tt], row stride TILE+1 float2 to spread banks
    __shared__ float2 so[WARPS][32][TILE + 1];

    const int tid  = threadIdx.x;
    const int warp = tid >> 5;
    const int lane = tid & 31;
    const int b    = blockIdx.x * BLOCK + tid;
    const bool active = (b < batch);
    const int stride = iters + 1;

    float A0=0,A1=0,A2=0,A3=0,A4=0,A5=0,B0=0,B1=0,B2=0,B3=0,B4=0,B5=0,p=0;
    if (active) {
        const float4* c4 = reinterpret_cast<const float4*>(coef + (size_t)b * 12);
        float4 ca = c4[0], cb = c4[1], cc = c4[2];
        A0=ca.x; A1=ca.y; A2=ca.z; A3=ca.w; A4=cb.x; A5=cb.y;
        B0=cb.z; B1=cb.w; B2=cc.x; B3=cc.y; B4=cc.z; B5=cc.w;
        float j0 = fabsf(A0*A3 - A1*A2);
        float j1 = fabsf(B0*B3 - B1*B2);
        p = j0 / (j0 + j1);
        out[(size_t)b * stride] = make_float2(0.05f, 0.05f);  // initial point
    }

    float x = 0.05f, y = 0.05f;

    const int warp_b0 = blockIdx.x * BLOCK + warp * 32;  // first b of this warp
    const int nfull = iters / TILE;

    for (int tile = 0; tile < nfull; ++tile) {
        const int t0 = tile * TILE;

        // phase 1: h tile into registers (16 independent coalesced LDGs)
        float hv[TILE];
        if (active) {
            #pragma unroll
            for (int tt = 0; tt < TILE; ++tt)
                hv[tt] = __ldg(h + (size_t)(t0 + tt) * batch + b);
        }

        // phase 2: recurrence, stage to per-warp smem
        if (active) {
            #pragma unroll
            for (int tt = 0; tt < TILE; ++tt) {
                float xA = fmaf(A0, x, fmaf(A1, y, A4));
                float yA = fmaf(A2, x, fmaf(A3, y, A5));
                float xB = fmaf(B0, x, fmaf(B1, y, B4));
                float yB = fmaf(B2, x, fmaf(B3, y, B5));
                bool m = hv[tt] > p;
                x = m ? xB : xA;
                y = m ? yB : yA;
                so[warp][lane][tt] = make_float2(x, y);
            }
        }
        __syncwarp();

        // phase 3: coalesced flush. Half-warp h writes row (2k + h)'s 16 float2.
        {
            const int rhalf = lane >> 4;       // 0/1
            const int tt    = lane & 15;
            #pragma unroll
            for (int k = 0; k < TILE; ++k) {
                int bl = 2 * k + rhalf;        // 0..31
                int bg = warp_b0 + bl;
                if (bg < batch)
                    out[(size_t)bg * stride + 1 + t0 + tt] = so[warp][bl][tt];
            }
        }
        __syncwarp();
    }

    // tail tile (iters % TILE steps), generic slow path
    const int trem = iters - nfull * TILE;
    if (trem > 0) {
        const int t0 = nfull * TILE;
        if (active) {
            for (int tt = 0; tt < trem; ++tt) {
                float ht = __ldg(h + (size_t)(t0 + tt) * batch + b);
                float xA = fmaf(A0, x, fmaf(A1, y, A4));
                float yA = fmaf(A2, x, fmaf(A3, y, A5));
                float xB = fmaf(B0, x, fmaf(B1, y, B4));
                float yB = fmaf(B2, x, fmaf(B3, y, B5));
                bool m = ht > p;
                x = m ? xB : xA;
                y = m ? yB : yA;
                so[warp][lane][tt] = make_float2(x, y);
            }
        }
        __syncwarp();
        for (int bl = 0; bl < 32; ++bl) {
            int bg = warp_b0 + bl;
            if (lane < trem && bg < batch)
                out[(size_t)bg * stride + 1 + t0 + lane] = so[warp][bl][lane];
        }
    }
}

extern "C" void kernel_launch(void* const* d_in, const int* in_sizes, int n_in,
                              void* d_out, int out_size) {
    const float* coef = (const float*)d_in[0];
    const float* h    = (const float*)d_in[1];
    float2* out       = (float2*)d_out;

    int batch = in_sizes[0] / 12;
    int iters = in_sizes[1] / batch;

    int blocks = (batch + BLOCK - 1) / BLOCK;
    ifs_traj_kernel<<<blocks, BLOCK>>>(coef, h, out, batch, iters);
}

// round 4
// speedup vs baseline: 3.2757x; 1.0619x over previous
#include <cuda_runtime.h>
#include <cstdint>

// IFS trajectory kernel, per-warp time-tiled + cp.async double-buffered h.
// inputs: d_in[0] = coef (BATCH, 12) f32, d_in[1] = h (ITERS, BATCH) f32
// output: (BATCH, ITERS+1, 2) f32
//
// Per tile of TILE=16 steps:
//   prefetch tile t+1's h into smem via cp.async.cg (16B chunks) while
//   computing tile t from the other buffer; (x,y) staged per-warp in smem,
//   flushed as contiguous 128B segments per half-warp.

#define BLOCK 256
#define TILE  16
#define WARPS (BLOCK / 32)
#define NBUF  2

__device__ __forceinline__ void cp_async16(uint32_t saddr, const void* gptr) {
    asm volatile("cp.async.cg.shared.global [%0], [%1], 16;\n"
                 :: "r"(saddr), "l"(gptr));
}
__device__ __forceinline__ void cp_commit() {
    asm volatile("cp.async.commit_group;\n");
}
template <int N>
__device__ __forceinline__ void cp_wait() {
    asm volatile("cp.async.wait_group %0;\n" :: "n"(N));
}

__global__ __launch_bounds__(BLOCK, 3) void ifs_traj_kernel(
    const float* __restrict__ coef,
    const float* __restrict__ h,
    float2* __restrict__ out,
    int batch, int iters)
{
    __shared__ float  sh[NBUF][TILE][BLOCK];   // 2 * 16KB
    __shared__ float2 so[WARPS][32][TILE + 1]; // ~35KB, +1 pad vs conflicts

    const int tid  = threadIdx.x;
    const int warp = tid >> 5;
    const int lane = tid & 31;
    const int block_b0 = blockIdx.x * BLOCK;
    const int b    = block_b0 + tid;
    const bool active = (b < batch);
    const int stride = iters + 1;
    const int nfull = iters / TILE;

    // ---- per-element setup ----
    float A0=0,A1=0,A2=0,A3=0,A4=0,A5=0,B0=0,B1=0,B2=0,B3=0,B4=0,B5=0,p=0;
    if (active) {
        const float4* c4 = reinterpret_cast<const float4*>(coef + (size_t)b * 12);
        float4 ca = c4[0], cb = c4[1], cc = c4[2];
        A0=ca.x; A1=ca.y; A2=ca.z; A3=ca.w; A4=cb.x; A5=cb.y;
        B0=cb.z; B1=cb.w; B2=cc.x; B3=cc.y; B4=cc.z; B5=cc.w;
        float j0 = fabsf(A0*A3 - A1*A2);
        float j1 = fabsf(B0*B3 - B1*B2);
        p = j0 / (j0 + j1);
    }
    float x = 0.05f, y = 0.05f;

    // ---- h-tile prefetch: 1024 float4 chunks / block, 4 per thread ----
    // flat chunk id -> row = flat/64 (64 float4 per 256-float row), col4 = flat%64
    auto prefetch = [&](int tile, int buf) {
        const float* gbase = h + (size_t)(tile * TILE) * batch + block_b0;
        uint32_t sbase = (uint32_t)__cvta_generic_to_shared(&sh[buf][0][0]);
        #pragma unroll
        for (int i = 0; i < 4; ++i) {
            int flat = tid + i * BLOCK;
            int row  = flat >> 6;
            int gb   = (flat & 63) << 2;
            if (block_b0 + gb < batch)   // batch % 4 == 0 assumed for alignment
                cp_async16(sbase + (uint32_t)((row * BLOCK + gb) << 2),
                           gbase + (size_t)row * batch + gb);
        }
        cp_commit();
    };

    const int warp_b0 = block_b0 + warp * 32;

    if (nfull > 0) prefetch(0, 0);

    for (int tile = 0; tile < nfull; ++tile) {
        const int t0  = tile * TILE;
        const int buf = tile & 1;

        if (tile + 1 < nfull) {
            prefetch(tile + 1, buf ^ 1);
            cp_wait<1>();
        } else {
            cp_wait<0>();
        }
        __syncthreads();   // h tile `tile` visible to all

        // ---- recurrence out of smem, stage per-warp ----
        if (active) {
            #pragma unroll
            for (int tt = 0; tt < TILE; ++tt) {
                float ht = sh[buf][tt][tid];
                float xA = fmaf(A0, x, fmaf(A1, y, A4));
                float yA = fmaf(A2, x, fmaf(A3, y, A5));
                float xB = fmaf(B0, x, fmaf(B1, y, B4));
                float yB = fmaf(B2, x, fmaf(B3, y, B5));
                bool m = ht > p;
                x = m ? xB : xA;
                y = m ? yB : yA;
                so[warp][lane][tt] = make_float2(x, y);
            }
        }
        __syncwarp();

        // ---- coalesced flush: half-warp writes one b's 16 float2 (128B) ----
        {
            const int rhalf = lane >> 4;
            const int tt    = lane & 15;
            #pragma unroll
            for (int k = 0; k < TILE; ++k) {
                int bl = 2 * k + rhalf;
                int bg = warp_b0 + bl;
                if (bg < batch) {
                    size_t rowbase = (size_t)bg * stride;
                    out[rowbase + 1 + t0 + tt] = so[warp][bl][tt];
                    if (tile == 0 && tt == 0)
                        out[rowbase] = make_float2(0.05f, 0.05f); // initial point
                }
            }
        }
        __syncthreads();   // all reads of sh[buf] done before it is refilled
    }

    // ---- tail tile (iters % TILE) ----
    const int trem = iters - nfull * TILE;
    if (trem > 0) {
        const int t0 = nfull * TILE;
        if (active) {
            for (int tt = 0; tt < trem; ++tt) {
                float ht = __ldg(h + (size_t)(t0 + tt) * batch + b);
                float xA = fmaf(A0, x, fmaf(A1, y, A4));
                float yA = fmaf(A2, x, fmaf(A3, y, A5));
                float xB = fmaf(B0, x, fmaf(B1, y, B4));
                float yB = fmaf(B2, x, fmaf(B3, y, B5));
                bool m = ht > p;
                x = m ? xB : xA;
                y = m ? yB : yA;
                so[warp][lane][tt] = make_float2(x, y);
            }
        }
        __syncwarp();
        for (int bl = 0; bl < 32; ++bl) {
            int bg = warp_b0 + bl;
            if (lane < trem && bg < batch)
                out[(size_t)bg * stride + 1 + t0 + lane] = so[warp][bl][lane];
        }
    }
}

extern "C" void kernel_launch(void* const* d_in, const int* in_sizes, int n_in,
                              void* d_out, int out_size) {
    const float* coef = (const float*)d_in[0];
    const float* h    = (const float*)d_in[1];
    float2* out       = (float2*)d_out;

    int batch = in_sizes[0] / 12;
    int iters = in_sizes[1] / batch;

    int blocks = (batch + BLOCK - 1) / BLOCK;
    ifs_traj_kernel<<<blocks, BLOCK>>>(coef, h, out, batch, iters);
}